// round 7
// baseline (speedup 1.0000x reference)
#include <cuda_runtime.h>
#include <cuda_bf16.h>
#include <cstdint>

#define DN   128
#define DE   64
#define NMAX 50000

__device__ float g_sums[(size_t)NMAX * DN];
__device__ float g_cnt[NMAX];
__device__ int   g_is64;

__device__ __forceinline__ float lrelu(float v) { return v > 0.f ? v : 0.01f * v; }

__device__ __forceinline__ uint32_t smem_u32(const void* p) {
    uint32_t a;
    asm("{ .reg .u64 t; cvta.to.shared.u64 t, %1; cvt.u32.u64 %0, t; }" : "=r"(a) : "l"(p));
    return a;
}

__device__ __forceinline__ void ldsm4(uint32_t addr, uint32_t r[4]) {
    asm volatile("ldmatrix.sync.aligned.m8n8.x4.shared.b16 {%0,%1,%2,%3}, [%4];"
                 : "=r"(r[0]), "=r"(r[1]), "=r"(r[2]), "=r"(r[3]) : "r"(addr));
}

__device__ __forceinline__ void mma16816(float c[4], const uint32_t a[4], const uint32_t b[2]) {
    asm volatile("mma.sync.aligned.m16n8k16.row.col.f32.bf16.bf16.f32 "
                 "{%0,%1,%2,%3}, {%4,%5,%6,%7}, {%8,%9}, {%0,%1,%2,%3};"
                 : "+f"(c[0]), "+f"(c[1]), "+f"(c[2]), "+f"(c[3])
                 : "r"(a[0]), "r"(a[1]), "r"(a[2]), "r"(a[3]), "r"(b[0]), "r"(b[1]));
}

__device__ __forceinline__ void split2(float v, unsigned short& h, unsigned short& l) {
    __nv_bfloat16 hb = __float2bfloat16(v);
    __nv_bfloat16 lb = __float2bfloat16(v - __bfloat162float(hb));
    h = *(unsigned short*)&hb;
    l = *(unsigned short*)&lb;
}
__device__ __forceinline__ void split4(float4 v, uint32_t& h01, uint32_t& h23,
                                       uint32_t& l01, uint32_t& l23) {
    __nv_bfloat162 a = __floats2bfloat162_rn(v.x, v.y);
    __nv_bfloat162 b = __floats2bfloat162_rn(v.z, v.w);
    __nv_bfloat162 c = __floats2bfloat162_rn(v.x - __low2float(a), v.y - __high2float(a));
    __nv_bfloat162 d = __floats2bfloat162_rn(v.z - __low2float(b), v.w - __high2float(b));
    h01 = *(uint32_t*)&a; h23 = *(uint32_t*)&b;
    l01 = *(uint32_t*)&c; l23 = *(uint32_t*)&d;
}

// 3-term split GEMM, warp tile 16x32. KB = row stride bytes, KS = K/16 steps.
template <int KB, int KS>
__device__ __forceinline__ void mma_core(uint32_t aH, uint32_t aL, uint32_t bH, uint32_t bL,
                                         int m0, int n0, int lane, float c[4][4])
{
#pragma unroll
    for (int nt = 0; nt < 4; ++nt)
#pragma unroll
        for (int j = 0; j < 4; ++j) c[nt][j] = 0.f;

    uint32_t rA = lane & 15;
    uint32_t kA = (lane >> 4) << 4;
    uint32_t xA = (rA & 7) << 4;
    uint32_t rB = ((lane >> 4) & 1) * 8 + (lane & 7);
    uint32_t kB = ((lane >> 3) & 1) << 4;
    uint32_t xB = (rB & 7) << 4;
    uint32_t aRH = aH + (m0 + rA) * KB;
    uint32_t aRL = aL + (m0 + rA) * KB;
    uint32_t bRH = bH + (n0 + rB) * KB;
    uint32_t bRL = bL + (n0 + rB) * KB;

#pragma unroll 2
    for (int ks = 0; ks < KS; ++ks) {
        uint32_t colA = (((uint32_t)ks * 32) | kA) ^ xA;
        uint32_t colB = (((uint32_t)ks * 32) | kB) ^ xB;
        uint32_t ah[4], al[4], bh[2][4], bl[2][4];
        ldsm4(aRH + colA, ah);
        ldsm4(aRL + colA, al);
#pragma unroll
        for (int p = 0; p < 2; ++p) {
            ldsm4(bRH + p * 16 * KB + colB, bh[p]);
            ldsm4(bRL + p * 16 * KB + colB, bl[p]);
        }
#pragma unroll
        for (int nt = 0; nt < 4; ++nt) {
            const uint32_t* bbh = &bh[nt >> 1][(nt & 1) * 2];
            const uint32_t* bbl = &bl[nt >> 1][(nt & 1) * 2];
            mma16816(c[nt], ah, bbh);
            mma16816(c[nt], al, bbh);
            mma16816(c[nt], ah, bbl);
        }
    }
}

// ---------------- small kernels -------------------------------------------------
__global__ void detect_kernel(const unsigned* __restrict__ w, int E)
{
    __shared__ unsigned accsh;
    if (threadIdx.x == 0) accsh = 0u;
    __syncthreads();
    int nscan = 4096; if (nscan > E) nscan = E;
    unsigned nz = 0;
    for (int i = threadIdx.x; i < nscan; i += blockDim.x) nz |= w[2 * i + 1];
#pragma unroll
    for (int o = 16; o > 0; o >>= 1) nz |= __shfl_xor_sync(0xffffffffu, nz, o);
    if ((threadIdx.x & 31) == 0) atomicOr(&accsh, nz);
    __syncthreads();
    if (threadIdx.x == 0) g_is64 = (accsh == 0u) ? 1 : 0;
}

__global__ void zero_kernel(int N)
{
    int tid = blockIdx.x * blockDim.x + threadIdx.x;
    int stride = gridDim.x * blockDim.x;
    float4 z = make_float4(0.f, 0.f, 0.f, 0.f);
    float4* s4 = (float4*)g_sums;
    int n4 = N * (DN / 4);
    for (int i = tid; i < n4; i += stride) s4[i] = z;
    for (int i = tid; i < N; i += stride) g_cnt[i] = 0.f;
}

// ---------------- edge kernel: 512 thr, 64-edge tiles, register epilogue --------
#define E_BH   0
#define E_BL   49152
#define E_A    98304
#define E_AL   122880
#define E_PART 147456
#define E_P    149504
#define SMEM_EDGE 151040

__global__ void __launch_bounds__(512, 1) edge_kernel(
    const float* __restrict__ x, const void* __restrict__ eidx,
    const float* __restrict__ ea, const float* __restrict__ W1,
    const float* __restrict__ b1, const float* __restrict__ g1,
    const float* __restrict__ be1, int N, int E)
{
    extern __shared__ char smem[];
    const uint32_t sb = smem_u32(smem);
    float* sPart = (float*)(smem + E_PART);   // [64 rows][4 ngroups] float2
    float* sP    = (float*)(smem + E_P);

    int tid = threadIdx.x, wid = tid >> 5, lane = tid & 31;
    int m0 = (wid >> 2) * 16, n0 = (wid & 3) * 32;
    int rlo = lane >> 2, cpid = lane & 3;
    int ng = wid & 3;

    // one-time: W1 (192 x 128) -> Bt[n][k] bf16 hi/lo, swizzled (row stride 384B)
    for (int i = tid; i < 192 * 32; i += 512) {
        int k = i >> 5, n4 = (i & 31) << 2;
        float4 w = *(const float4*)&W1[(size_t)k * DN + n4];
#pragma unroll
        for (int j = 0; j < 4; ++j) {
            int n = n4 + j;
            unsigned short h, l;
            split2((&w.x)[j], h, l);
            uint32_t a = sb + E_BH + n * 384 + (((uint32_t)(2 * k)) ^ (((uint32_t)(n & 7)) << 4));
            asm volatile("st.shared.b16 [%0], %1;" :: "r"(a), "h"(h));
            asm volatile("st.shared.b16 [%0], %1;" :: "r"(a + (E_BL - E_BH)), "h"(l));
        }
    }
    for (int i = tid; i < DN; i += 512) { sP[i] = b1[i]; sP[DN + i] = g1[i]; sP[2 * DN + i] = be1[i]; }
    __syncthreads();

    // per-thread LN params for owned columns (cols n0 + nt*8 + cpid*2, +1)
    float2 bbv[4], ggv[4], bev[4];
#pragma unroll
    for (int nt = 0; nt < 4; ++nt) {
        int col = n0 + nt * 8 + cpid * 2;
        bbv[nt] = *(const float2*)&sP[col];
        ggv[nt] = *(const float2*)&sP[DN + col];
        bev[nt] = *(const float2*)&sP[2 * DN + col];
    }

    const int is64 = g_is64;
    const long long* ei64 = (const long long*)eidx;
    const int*       ei32 = (const int*)eidx;

    int ntiles = (E + 63) >> 6;
    float4 v[6];

    // prologue: gather + convert tile t0
    int t = blockIdx.x;
    {
        int e0 = t << 6;
#pragma unroll
        for (int j = 0; j < 6; ++j) {
            int i = tid + (j << 9);
            int r = i / 48, q = i - r * 48;
            int e = e0 + r;
            float4 val = make_float4(0.f, 0.f, 0.f, 0.f);
            if (e < E) {
                if (q < 32) {
                    int ri = is64 ? (int)ei64[e] : ei32[e];
                    val = *(const float4*)&x[(size_t)ri * DN + q * 4];
                } else val = *(const float4*)&ea[(size_t)e * DE + (q - 32) * 4];
            }
            v[j] = val;
        }
#pragma unroll
        for (int j = 0; j < 6; ++j) {
            int i = tid + (j << 9);
            int r = i / 48, q = i - r * 48;
            uint32_t h01, h23, l01, l23;
            split4(v[j], h01, h23, l01, l23);
            uint32_t a = sb + E_A + r * 384 + (((uint32_t)(8 * q)) ^ (((uint32_t)(r & 7)) << 4));
            asm volatile("st.shared.v2.b32 [%0], {%1,%2};" :: "r"(a), "r"(h01), "r"(h23));
            asm volatile("st.shared.v2.b32 [%0], {%1,%2};" :: "r"(a + (E_AL - E_A)), "r"(l01), "r"(l23));
        }
    }
    __syncthreads();

    for (; t < ntiles; t += gridDim.x) {
        int tn = t + gridDim.x;
        // prefetch next tile into registers (LDG hides under mma)
        if (tn < ntiles) {
            int e0 = tn << 6;
#pragma unroll
            for (int j = 0; j < 6; ++j) {
                int i = tid + (j << 9);
                int r = i / 48, q = i - r * 48;
                int e = e0 + r;
                float4 val = make_float4(0.f, 0.f, 0.f, 0.f);
                if (e < E) {
                    if (q < 32) {
                        int ri = is64 ? (int)ei64[e] : ei32[e];
                        val = *(const float4*)&x[(size_t)ri * DN + q * 4];
                    } else val = *(const float4*)&ea[(size_t)e * DE + (q - 32) * 4];
                }
                v[j] = val;
            }
        }

        float c[4][4];
        mma_core<384, 12>(sb + E_A, sb + E_AL, sb + E_BH, sb + E_BL, m0, n0, lane, c);

        // LN partials: 4-lane group owns 32 cols of rows m0+rlo, m0+8+rlo
#pragma unroll
        for (int h = 0; h < 2; ++h) {
            float s = 0.f, q = 0.f;
#pragma unroll
            for (int nt = 0; nt < 4; ++nt) {
                float f0 = c[nt][2 * h]     + bbv[nt].x;
                float f1 = c[nt][2 * h + 1] + bbv[nt].y;
                s += f0 + f1;
                q = fmaf(f0, f0, fmaf(f1, f1, q));
            }
            s += __shfl_xor_sync(0xffffffffu, s, 1);
            q += __shfl_xor_sync(0xffffffffu, q, 1);
            s += __shfl_xor_sync(0xffffffffu, s, 2);
            q += __shfl_xor_sync(0xffffffffu, q, 2);
            if (cpid == 0) {
                int row = m0 + h * 8 + rlo;
                sPart[(row * 4 + ng) * 2]     = s;
                sPart[(row * 4 + ng) * 2 + 1] = q;
            }
        }
        __syncthreads();   // partials visible; all mma A-reads done

        // epilogue from registers + scatter
        {
            int e0 = t << 6;
#pragma unroll
            for (int h = 0; h < 2; ++h) {
                int row = m0 + h * 8 + rlo;
                float4 pa = *(const float4*)&sPart[row * 8];
                float4 pb = *(const float4*)&sPart[row * 8 + 4];
                float s = pa.x + pa.z + pb.x + pb.z;
                float q = pa.y + pa.w + pb.y + pb.w;
                const float inv = 0.0078125f;
                float mean = s * inv;
                float var  = fmaf(q, inv, -mean * mean);
                float rstd = rsqrtf(var + 1e-5f);
                int e = e0 + row;
                int ci = 0;
                if (e < E) ci = is64 ? (int)ei64[(size_t)E + e] : ei32[E + e];
#pragma unroll
                for (int nt = 0; nt < 4; ++nt) {
                    float f0 = c[nt][2 * h]     + bbv[nt].x;
                    float f1 = c[nt][2 * h + 1] + bbv[nt].y;
                    float o0 = lrelu(fmaf((f0 - mean) * rstd, ggv[nt].x, bev[nt].x));
                    float o1 = lrelu(fmaf((f1 - mean) * rstd, ggv[nt].y, bev[nt].y));
                    // pair lanes: even lane gets odd lane's pair -> red.v4
                    float p0 = __shfl_xor_sync(0xffffffffu, o0, 1);
                    float p1 = __shfl_xor_sync(0xffffffffu, o1, 1);
                    if ((cpid & 1) == 0 && e < E) {
                        int col = n0 + nt * 8 + (cpid & 2) * 2;
                        float* p = g_sums + (size_t)ci * DN + col;
                        asm volatile("red.global.add.v4.f32 [%0], {%1,%2,%3,%4};"
                                     :: "l"(p), "f"(o0), "f"(o1), "f"(p0), "f"(p1) : "memory");
                    }
                }
                if (cpid == 0 && ng == 0 && e < E) atomicAdd(g_cnt + ci, 1.0f);
            }
        }

        // convert prefetched regs -> A(tn)
        if (tn < ntiles) {
#pragma unroll
            for (int j = 0; j < 6; ++j) {
                int i = tid + (j << 9);
                int r = i / 48, q = i - r * 48;
                uint32_t h01, h23, l01, l23;
                split4(v[j], h01, h23, l01, l23);
                uint32_t a = sb + E_A + r * 384 + (((uint32_t)(8 * q)) ^ (((uint32_t)(r & 7)) << 4));
                asm volatile("st.shared.v2.b32 [%0], {%1,%2};" :: "r"(a), "r"(h01), "r"(h23));
                asm volatile("st.shared.v2.b32 [%0], {%1,%2};" :: "r"(a + (E_AL - E_A)), "r"(l01), "r"(l23));
            }
        }
        __syncthreads();   // A(tn) ready; partials consumed
    }
}

// ---------------- node kernel: same structure, residual + store -----------------
#define N_BH   0
#define N_BL   32768
#define N_A    65536
#define N_AL   81920
#define N_PART 98304
#define N_P    100352
#define SMEM_NODE 101888

__global__ void __launch_bounds__(512, 1) node_kernel(
    const float* __restrict__ x, const float* __restrict__ W2,
    const float* __restrict__ b2, const float* __restrict__ g2,
    const float* __restrict__ be2, float* __restrict__ out, int N)
{
    extern __shared__ char smem[];
    const uint32_t sb = smem_u32(smem);
    float* sPart = (float*)(smem + N_PART);
    float* sP    = (float*)(smem + N_P);

    int tid = threadIdx.x, wid = tid >> 5, lane = tid & 31;
    int m0 = (wid >> 2) * 16, n0 = (wid & 3) * 32;
    int rlo = lane >> 2, cpid = lane & 3;
    int ng = wid & 3;

    for (int i = tid; i < 128 * 32; i += 512) {
        int k = i >> 5, n4 = (i & 31) << 2;
        float4 w = *(const float4*)&W2[(size_t)k * DN + n4];
#pragma unroll
        for (int j = 0; j < 4; ++j) {
            int n = n4 + j;
            unsigned short h, l;
            split2((&w.x)[j], h, l);
            uint32_t a = sb + N_BH + n * 256 + (((uint32_t)(2 * k)) ^ (((uint32_t)(n & 7)) << 4));
            asm volatile("st.shared.b16 [%0], %1;" :: "r"(a), "h"(h));
            asm volatile("st.shared.b16 [%0], %1;" :: "r"(a + (N_BL - N_BH)), "h"(l));
        }
    }
    for (int i = tid; i < DN; i += 512) { sP[i] = b2[i]; sP[DN + i] = g2[i]; sP[2 * DN + i] = be2[i]; }
    __syncthreads();

    float2 bbv[4], ggv[4], bev[4];
#pragma unroll
    for (int nt = 0; nt < 4; ++nt) {
        int col = n0 + nt * 8 + cpid * 2;
        bbv[nt] = *(const float2*)&sP[col];
        ggv[nt] = *(const float2*)&sP[DN + col];
        bev[nt] = *(const float2*)&sP[2 * DN + col];
    }

    int ntiles = (N + 63) >> 6;
    float4 v[4];

    int t = blockIdx.x;
    {
        int nb = t << 6;
#pragma unroll
        for (int j = 0; j < 4; ++j) {
            int i = tid + (j << 9);
            int r = i >> 5, q = i & 31;
            int n = nb + r;
            float4 val = make_float4(0.f, 0.f, 0.f, 0.f);
            if (n < N) {
                float sc = 1.0f / fmaxf(g_cnt[n], 1.0f);
                val = *(const float4*)&g_sums[(size_t)n * DN + q * 4];
                val.x *= sc; val.y *= sc; val.z *= sc; val.w *= sc;
            }
            v[j] = val;
        }
#pragma unroll
        for (int j = 0; j < 4; ++j) {
            int i = tid + (j << 9);
            int r = i >> 5, q = i & 31;
            uint32_t h01, h23, l01, l23;
            split4(v[j], h01, h23, l01, l23);
            uint32_t a = sb + N_A + r * 256 + (((uint32_t)(8 * q)) ^ (((uint32_t)(r & 7)) << 4));
            asm volatile("st.shared.v2.b32 [%0], {%1,%2};" :: "r"(a), "r"(h01), "r"(h23));
            asm volatile("st.shared.v2.b32 [%0], {%1,%2};" :: "r"(a + (N_AL - N_A)), "r"(l01), "r"(l23));
        }
    }
    __syncthreads();

    for (; t < ntiles; t += gridDim.x) {
        int tn = t + gridDim.x;
        if (tn < ntiles) {
            int nb = tn << 6;
#pragma unroll
            for (int j = 0; j < 4; ++j) {
                int i = tid + (j << 9);
                int r = i >> 5, q = i & 31;
                int n = nb + r;
                float4 val = make_float4(0.f, 0.f, 0.f, 0.f);
                if (n < N) {
                    float sc = 1.0f / fmaxf(g_cnt[n], 1.0f);
                    val = *(const float4*)&g_sums[(size_t)n * DN + q * 4];
                    val.x *= sc; val.y *= sc; val.z *= sc; val.w *= sc;
                }
                v[j] = val;
            }
        }

        float c[4][4];
        mma_core<256, 8>(sb + N_A, sb + N_AL, sb + N_BH, sb + N_BL, m0, n0, lane, c);

#pragma unroll
        for (int h = 0; h < 2; ++h) {
            float s = 0.f, q = 0.f;
#pragma unroll
            for (int nt = 0; nt < 4; ++nt) {
                float f0 = c[nt][2 * h]     + bbv[nt].x;
                float f1 = c[nt][2 * h + 1] + bbv[nt].y;
                s += f0 + f1;
                q = fmaf(f0, f0, fmaf(f1, f1, q));
            }
            s += __shfl_xor_sync(0xffffffffu, s, 1);
            q += __shfl_xor_sync(0xffffffffu, q, 1);
            s += __shfl_xor_sync(0xffffffffu, s, 2);
            q += __shfl_xor_sync(0xffffffffu, q, 2);
            if (cpid == 0) {
                int row = m0 + h * 8 + rlo;
                sPart[(row * 4 + ng) * 2]     = s;
                sPart[(row * 4 + ng) * 2 + 1] = q;
            }
        }
        __syncthreads();

        {
            int nb = t << 6;
#pragma unroll
            for (int h = 0; h < 2; ++h) {
                int row = m0 + h * 8 + rlo;
                float4 pa = *(const float4*)&sPart[row * 8];
                float4 pb = *(const float4*)&sPart[row * 8 + 4];
                float s = pa.x + pa.z + pb.x + pb.z;
                float q = pa.y + pa.w + pb.y + pb.w;
                const float inv = 0.0078125f;
                float mean = s * inv;
                float var  = fmaf(q, inv, -mean * mean);
                float rstd = rsqrtf(var + 1e-5f);
                int n = nb + row;
#pragma unroll
                for (int nt = 0; nt < 4; ++nt) {
                    float f0 = c[nt][2 * h]     + bbv[nt].x;
                    float f1 = c[nt][2 * h + 1] + bbv[nt].y;
                    float o0 = lrelu(fmaf((f0 - mean) * rstd, ggv[nt].x, bev[nt].x));
                    float o1 = lrelu(fmaf((f1 - mean) * rstd, ggv[nt].y, bev[nt].y));
                    float p0 = __shfl_xor_sync(0xffffffffu, o0, 1);
                    float p1 = __shfl_xor_sync(0xffffffffu, o1, 1);
                    if ((cpid & 1) == 0 && n < N) {
                        int col = n0 + nt * 8 + (cpid & 2) * 2;
                        float4 xr = *(const float4*)&x[(size_t)n * DN + col];
                        float r0 = lrelu(o0 + xr.x);
                        float r1 = lrelu(o1 + xr.y);
                        float r2 = lrelu(p0 + xr.z);
                        float r3 = lrelu(p1 + xr.w);
                        *(float4*)&out[(size_t)n * DN + col] = make_float4(r0, r1, r2, r3);
                    }
                }
            }
        }

        if (tn < ntiles) {
#pragma unroll
            for (int j = 0; j < 4; ++j) {
                int i = tid + (j << 9);
                int r = i >> 5, q = i & 31;
                uint32_t h01, h23, l01, l23;
                split4(v[j], h01, h23, l01, l23);
                uint32_t a = sb + N_A + r * 256 + (((uint32_t)(8 * q)) ^ (((uint32_t)(r & 7)) << 4));
                asm volatile("st.shared.v2.b32 [%0], {%1,%2};" :: "r"(a), "r"(h01), "r"(h23));
                asm volatile("st.shared.v2.b32 [%0], {%1,%2};" :: "r"(a + (N_AL - N_A)), "r"(l01), "r"(l23));
            }
        }
        __syncthreads();
    }
}

// ---------------- launch ----------------------------------------------------------
extern "C" void kernel_launch(void* const* d_in, const int* in_sizes, int n_in,
                              void* d_out, int out_size)
{
    const float* x   = (const float*)d_in[0];
    const void*  ei  = d_in[1];
    const float* ea  = (const float*)d_in[2];
    const float* W1  = (const float*)d_in[3];
    const float* b1  = (const float*)d_in[4];
    const float* g1  = (const float*)d_in[5];
    const float* be1 = (const float*)d_in[6];
    const float* W2  = (const float*)d_in[7];
    const float* b2  = (const float*)d_in[8];
    const float* g2  = (const float*)d_in[9];
    const float* be2 = (const float*)d_in[10];
    float* out = (float*)d_out;

    int N = in_sizes[0] / DN;
    int E = in_sizes[2] / DE;

    cudaFuncSetAttribute(edge_kernel, cudaFuncAttributeMaxDynamicSharedMemorySize, SMEM_EDGE);
    cudaFuncSetAttribute(node_kernel, cudaFuncAttributeMaxDynamicSharedMemorySize, SMEM_NODE);

    detect_kernel<<<1, 256>>>((const unsigned*)ei, E);
    zero_kernel<<<512, 256>>>(N);
    edge_kernel<<<148, 512, SMEM_EDGE>>>(x, ei, ea, W1, b1, g1, be1, N, E);
    node_kernel<<<148, 512, SMEM_NODE>>>(x, W2, b2, g2, be2, out, N);
}

// round 8
// speedup vs baseline: 1.0375x; 1.0375x over previous
#include <cuda_runtime.h>
#include <cuda_bf16.h>
#include <cstdint>

#define DN   128
#define DE   64
#define NMAX 50000

__device__ float g_sums[(size_t)NMAX * DN];
__device__ float g_cnt[NMAX];
__device__ int   g_is64;

__device__ __forceinline__ float lrelu(float v) { return v > 0.f ? v : 0.01f * v; }

__device__ __forceinline__ uint32_t smem_u32(const void* p) {
    uint32_t a;
    asm("{ .reg .u64 t; cvta.to.shared.u64 t, %1; cvt.u32.u64 %0, t; }" : "=r"(a) : "l"(p));
    return a;
}

__device__ __forceinline__ void ldsm4(uint32_t addr, uint32_t r[4]) {
    asm volatile("ldmatrix.sync.aligned.m8n8.x4.shared.b16 {%0,%1,%2,%3}, [%4];"
                 : "=r"(r[0]), "=r"(r[1]), "=r"(r[2]), "=r"(r[3]) : "r"(addr));
}

__device__ __forceinline__ void mma16816(float c[4], const uint32_t a[4], const uint32_t b[2]) {
    asm volatile("mma.sync.aligned.m16n8k16.row.col.f32.bf16.bf16.f32 "
                 "{%0,%1,%2,%3}, {%4,%5,%6,%7}, {%8,%9}, {%0,%1,%2,%3};"
                 : "+f"(c[0]), "+f"(c[1]), "+f"(c[2]), "+f"(c[3])
                 : "r"(a[0]), "r"(a[1]), "r"(a[2]), "r"(a[3]), "r"(b[0]), "r"(b[1]));
}

__device__ __forceinline__ void split2(float v, unsigned short& h, unsigned short& l) {
    __nv_bfloat16 hb = __float2bfloat16(v);
    __nv_bfloat16 lb = __float2bfloat16(v - __bfloat162float(hb));
    h = *(unsigned short*)&hb;
    l = *(unsigned short*)&lb;
}
__device__ __forceinline__ void split4(float4 v, uint32_t& h01, uint32_t& h23,
                                       uint32_t& l01, uint32_t& l23) {
    __nv_bfloat162 a = __floats2bfloat162_rn(v.x, v.y);
    __nv_bfloat162 b = __floats2bfloat162_rn(v.z, v.w);
    __nv_bfloat162 c = __floats2bfloat162_rn(v.x - __low2float(a), v.y - __high2float(a));
    __nv_bfloat162 d = __floats2bfloat162_rn(v.z - __low2float(b), v.w - __high2float(b));
    h01 = *(uint32_t*)&a; h23 = *(uint32_t*)&b;
    l01 = *(uint32_t*)&c; l23 = *(uint32_t*)&d;
}

// 3-term split GEMM, warp tile 16x32. KB = row stride bytes, KS = K/16 steps.
template <int KB, int KS>
__device__ __forceinline__ void mma_core(uint32_t aH, uint32_t aL, uint32_t bH, uint32_t bL,
                                         int m0, int n0, int lane, float c[4][4])
{
#pragma unroll
    for (int nt = 0; nt < 4; ++nt)
#pragma unroll
        for (int j = 0; j < 4; ++j) c[nt][j] = 0.f;

    uint32_t rA = lane & 15;
    uint32_t kA = (lane >> 4) << 4;
    uint32_t xA = (rA & 7) << 4;
    uint32_t rB = ((lane >> 4) & 1) * 8 + (lane & 7);
    uint32_t kB = ((lane >> 3) & 1) << 4;
    uint32_t xB = (rB & 7) << 4;
    uint32_t aRH = aH + (m0 + rA) * KB;
    uint32_t aRL = aL + (m0 + rA) * KB;
    uint32_t bRH = bH + (n0 + rB) * KB;
    uint32_t bRL = bL + (n0 + rB) * KB;

#pragma unroll 2
    for (int ks = 0; ks < KS; ++ks) {
        uint32_t colA = (((uint32_t)ks * 32) | kA) ^ xA;
        uint32_t colB = (((uint32_t)ks * 32) | kB) ^ xB;
        uint32_t ah[4], al[4], bh[2][4], bl[2][4];
        ldsm4(aRH + colA, ah);
        ldsm4(aRL + colA, al);
#pragma unroll
        for (int p = 0; p < 2; ++p) {
            ldsm4(bRH + p * 16 * KB + colB, bh[p]);
            ldsm4(bRL + p * 16 * KB + colB, bl[p]);
        }
#pragma unroll
        for (int nt = 0; nt < 4; ++nt) {
            const uint32_t* bbh = &bh[nt >> 1][(nt & 1) * 2];
            const uint32_t* bbl = &bl[nt >> 1][(nt & 1) * 2];
            mma16816(c[nt], ah, bbh);
            mma16816(c[nt], al, bbh);
            mma16816(c[nt], ah, bbl);
        }
    }
}

// ---------------- small kernels -------------------------------------------------
__global__ void detect_kernel(const unsigned* __restrict__ w, int E)
{
    __shared__ unsigned accsh;
    if (threadIdx.x == 0) accsh = 0u;
    __syncthreads();
    int nscan = 4096; if (nscan > E) nscan = E;
    unsigned nz = 0;
    for (int i = threadIdx.x; i < nscan; i += blockDim.x) nz |= w[2 * i + 1];
#pragma unroll
    for (int o = 16; o > 0; o >>= 1) nz |= __shfl_xor_sync(0xffffffffu, nz, o);
    if ((threadIdx.x & 31) == 0) atomicOr(&accsh, nz);
    __syncthreads();
    if (threadIdx.x == 0) g_is64 = (accsh == 0u) ? 1 : 0;
}

__global__ void zero_kernel(int N)
{
    int tid = blockIdx.x * blockDim.x + threadIdx.x;
    int stride = gridDim.x * blockDim.x;
    float4 z = make_float4(0.f, 0.f, 0.f, 0.f);
    float4* s4 = (float4*)g_sums;
    int n4 = N * (DN / 4);
    for (int i = tid; i < n4; i += stride) s4[i] = z;
    for (int i = tid; i < N; i += stride) g_cnt[i] = 0.f;
}

// ---------------- edge kernel: 512 thr, 64-edge tiles, double-buffered A --------
// smem: B_h 48K | B_l 48K | A0 h/l 48K | A1 h/l 48K | C 33K | params
#define E_BH 0
#define E_BL 49152
#define E_A0 98304          // buffer b: hi = E_A0 + b*49152, lo = hi + 24576
#define E_C  196608
#define E_P  230400
#define SMEM_EDGE 231936
#define CSTRIDE 132

__global__ void __launch_bounds__(512, 1) edge_kernel(
    const float* __restrict__ x, const void* __restrict__ eidx,
    const float* __restrict__ ea, const float* __restrict__ W1,
    const float* __restrict__ b1, const float* __restrict__ g1,
    const float* __restrict__ be1, int N, int E)
{
    extern __shared__ char smem[];
    const uint32_t sb = smem_u32(smem);
    float* sC = (float*)(smem + E_C);
    float* sP = (float*)(smem + E_P);

    int tid = threadIdx.x, wid = tid >> 5, lane = tid & 31;
    int m0 = (wid >> 2) * 16, n0 = (wid & 3) * 32;

    // one-time: W1 (192 x 128) -> Bt[n][k] bf16 hi/lo, swizzled (row stride 384B)
    for (int i = tid; i < 192 * 32; i += 512) {
        int k = i >> 5, n4 = (i & 31) << 2;
        float4 w = *(const float4*)&W1[(size_t)k * DN + n4];
#pragma unroll
        for (int j = 0; j < 4; ++j) {
            int n = n4 + j;
            unsigned short h, l;
            split2((&w.x)[j], h, l);
            uint32_t a = sb + E_BH + n * 384 + (((uint32_t)(2 * k)) ^ (((uint32_t)(n & 7)) << 4));
            asm volatile("st.shared.b16 [%0], %1;" :: "r"(a), "h"(h));
            asm volatile("st.shared.b16 [%0], %1;" :: "r"(a + (E_BL - E_BH)), "h"(l));
        }
    }
    for (int i = tid; i < DN; i += 512) { sP[i] = b1[i]; sP[DN + i] = g1[i]; sP[2 * DN + i] = be1[i]; }

    const int is64 = g_is64;
    const long long* ei64 = (const long long*)eidx;
    const int*       ei32 = (const int*)eidx;

    int ntiles = (E + 63) >> 6;
    float4 v[6];
    // per-thread fixed coordinates in the 64x192 A tile
    int rr[6], qq6[6];
#pragma unroll
    for (int j = 0; j < 6; ++j) {
        int i = tid + (j << 9);
        rr[j] = i / 48; qq6[j] = i - rr[j] * 48;
    }

    // gather tile into v
    auto GATHER = [&](int tt) {
        int e0 = tt << 6;
#pragma unroll
        for (int j = 0; j < 6; ++j) {
            int e = e0 + rr[j];
            float4 val = make_float4(0.f, 0.f, 0.f, 0.f);
            if (e < E) {
                if (qq6[j] < 32) {
                    int ri = is64 ? (int)ei64[e] : ei32[e];
                    val = *(const float4*)&x[(size_t)ri * DN + qq6[j] * 4];
                } else val = *(const float4*)&ea[(size_t)e * DE + (qq6[j] - 32) * 4];
            }
            v[j] = val;
        }
    };
    // convert v into A buffer b
    auto CONVERT = [&](int b) {
        uint32_t baseH = sb + E_A0 + (uint32_t)b * 49152u;
#pragma unroll
        for (int j = 0; j < 6; ++j) {
            uint32_t h01, h23, l01, l23;
            split4(v[j], h01, h23, l01, l23);
            uint32_t a = baseH + rr[j] * 384 +
                         (((uint32_t)(8 * qq6[j])) ^ (((uint32_t)(rr[j] & 7)) << 4));
            asm volatile("st.shared.v2.b32 [%0], {%1,%2};" :: "r"(a), "r"(h01), "r"(h23));
            asm volatile("st.shared.v2.b32 [%0], {%1,%2};" :: "r"(a + 24576), "r"(l01), "r"(l23));
        }
    };

    // prologue: A[0] <- t0 ; v <- t1
    int t = blockIdx.x;
    if (t < ntiles) {
        GATHER(t);
        CONVERT(0);
        if (t + gridDim.x < ntiles) GATHER(t + gridDim.x);
    }
    __syncthreads();

    int cur = 0;
    for (; t < ntiles; t += gridDim.x) {
        int tn  = t + gridDim.x;
        int tnn = tn + gridDim.x;

        // convert v (tile tn) into the other buffer — off the critical path
        if (tn < ntiles) CONVERT(cur ^ 1);
        // prefetch tile t+2 (full tile of latency cover)
        if (tnn < ntiles) GATHER(tnn);

        float c[4][4];
        uint32_t aH = sb + E_A0 + (uint32_t)cur * 49152u;
        mma_core<384, 12>(aH, aH + 24576, sb + E_BH, sb + E_BL, m0, n0, lane, c);

        // store C
        int rlo = lane >> 2, cp = (lane & 3) * 2;
#pragma unroll
        for (int nt = 0; nt < 4; ++nt) {
            int row = m0 + rlo, col = n0 + nt * 8 + cp;
            *(float2*)&sC[row * CSTRIDE + col]       = make_float2(c[nt][0], c[nt][1]);
            *(float2*)&sC[(row + 8) * CSTRIDE + col] = make_float2(c[nt][2], c[nt][3]);
        }
        __syncthreads();   // C + A[cur^1] visible; all mma A-reads done

        // epilogue: warp owns rows [4*wid, 4*wid+4)
        {
            int e0 = t << 6;
            int c0 = lane * 4;
            float4 bb  = *(const float4*)&sP[c0];
            float4 gg  = *(const float4*)&sP[DN + c0];
            float4 beb = *(const float4*)&sP[2 * DN + c0];
#pragma unroll
            for (int j = 0; j < 4; ++j) {
                int r = wid * 4 + j;
                int e = e0 + r;
                float4 cv = *(const float4*)&sC[r * CSTRIDE + c0];
                float v0 = cv.x + bb.x, v1 = cv.y + bb.y, v2 = cv.z + bb.z, v3 = cv.w + bb.w;
                float s = v0 + v1 + v2 + v3;
                float q = fmaf(v0, v0, fmaf(v1, v1, fmaf(v2, v2, v3 * v3)));
#pragma unroll
                for (int o = 16; o > 0; o >>= 1) {
                    s += __shfl_xor_sync(0xffffffffu, s, o);
                    q += __shfl_xor_sync(0xffffffffu, q, o);
                }
                const float inv = 0.0078125f;
                float mean = s * inv;
                float var  = fmaf(q, inv, -mean * mean);
                float rstd = rsqrtf(var + 1e-5f);
                float o0 = lrelu(fmaf((v0 - mean) * rstd, gg.x, beb.x));
                float o1 = lrelu(fmaf((v1 - mean) * rstd, gg.y, beb.y));
                float o2 = lrelu(fmaf((v2 - mean) * rstd, gg.z, beb.z));
                float o3 = lrelu(fmaf((v3 - mean) * rstd, gg.w, beb.w));
                if (e < E) {
                    int ci = is64 ? (int)ei64[(size_t)E + e] : ei32[E + e];
                    float* p = g_sums + (size_t)ci * DN + c0;
                    asm volatile("red.global.add.v4.f32 [%0], {%1,%2,%3,%4};"
                                 :: "l"(p), "f"(o0), "f"(o1), "f"(o2), "f"(o3) : "memory");
                    if (lane == 0) atomicAdd(g_cnt + ci, 1.0f);
                }
            }
        }
        __syncthreads();   // C reads done before next overwrite
        cur ^= 1;
    }
}

// ---------------- node kernel: same double-buffer pipeline ----------------------
#define N_BH 0
#define N_BL 32768
#define N_A0 65536          // buffer b: hi = N_A0 + b*32768, lo = hi + 16384
#define N_C  131072
#define N_P  164864
#define SMEM_NODE 166400

__global__ void __launch_bounds__(512, 1) node_kernel(
    const float* __restrict__ x, const float* __restrict__ W2,
    const float* __restrict__ b2, const float* __restrict__ g2,
    const float* __restrict__ be2, float* __restrict__ out, int N)
{
    extern __shared__ char smem[];
    const uint32_t sb = smem_u32(smem);
    float* sC = (float*)(smem + N_C);
    float* sP = (float*)(smem + N_P);

    int tid = threadIdx.x, wid = tid >> 5, lane = tid & 31;
    int m0 = (wid >> 2) * 16, n0 = (wid & 3) * 32;

    for (int i = tid; i < 128 * 32; i += 512) {
        int k = i >> 5, n4 = (i & 31) << 2;
        float4 w = *(const float4*)&W2[(size_t)k * DN + n4];
#pragma unroll
        for (int j = 0; j < 4; ++j) {
            int n = n4 + j;
            unsigned short h, l;
            split2((&w.x)[j], h, l);
            uint32_t a = sb + N_BH + n * 256 + (((uint32_t)(2 * k)) ^ (((uint32_t)(n & 7)) << 4));
            asm volatile("st.shared.b16 [%0], %1;" :: "r"(a), "h"(h));
            asm volatile("st.shared.b16 [%0], %1;" :: "r"(a + (N_BL - N_BH)), "h"(l));
        }
    }
    for (int i = tid; i < DN; i += 512) { sP[i] = b2[i]; sP[DN + i] = g2[i]; sP[2 * DN + i] = be2[i]; }

    int ntiles = (N + 63) >> 6;
    float4 v[4];
    int rr[4], qq4[4];
#pragma unroll
    for (int j = 0; j < 4; ++j) {
        int i = tid + (j << 9);
        rr[j] = i >> 5; qq4[j] = i & 31;
    }

    auto GATHER = [&](int tt) {
        int nb = tt << 6;
#pragma unroll
        for (int j = 0; j < 4; ++j) {
            int n = nb + rr[j];
            float4 val = make_float4(0.f, 0.f, 0.f, 0.f);
            if (n < N) {
                float sc = 1.0f / fmaxf(g_cnt[n], 1.0f);
                val = *(const float4*)&g_sums[(size_t)n * DN + qq4[j] * 4];
                val.x *= sc; val.y *= sc; val.z *= sc; val.w *= sc;
            }
            v[j] = val;
        }
    };
    auto CONVERT = [&](int b) {
        uint32_t baseH = sb + N_A0 + (uint32_t)b * 32768u;
#pragma unroll
        for (int j = 0; j < 4; ++j) {
            uint32_t h01, h23, l01, l23;
            split4(v[j], h01, h23, l01, l23);
            uint32_t a = baseH + rr[j] * 256 +
                         (((uint32_t)(8 * qq4[j])) ^ (((uint32_t)(rr[j] & 7)) << 4));
            asm volatile("st.shared.v2.b32 [%0], {%1,%2};" :: "r"(a), "r"(h01), "r"(h23));
            asm volatile("st.shared.v2.b32 [%0], {%1,%2};" :: "r"(a + 16384), "r"(l01), "r"(l23));
        }
    };

    int t = blockIdx.x;
    if (t < ntiles) {
        GATHER(t);
        CONVERT(0);
        if (t + gridDim.x < ntiles) GATHER(t + gridDim.x);
    }
    __syncthreads();

    int cur = 0;
    for (; t < ntiles; t += gridDim.x) {
        int tn  = t + gridDim.x;
        int tnn = tn + gridDim.x;

        if (tn < ntiles) CONVERT(cur ^ 1);
        if (tnn < ntiles) GATHER(tnn);

        float c[4][4];
        uint32_t aH = sb + N_A0 + (uint32_t)cur * 32768u;
        mma_core<256, 8>(aH, aH + 16384, sb + N_BH, sb + N_BL, m0, n0, lane, c);

        int rlo = lane >> 2, cp = (lane & 3) * 2;
#pragma unroll
        for (int nt = 0; nt < 4; ++nt) {
            int row = m0 + rlo, col = n0 + nt * 8 + cp;
            *(float2*)&sC[row * CSTRIDE + col]       = make_float2(c[nt][0], c[nt][1]);
            *(float2*)&sC[(row + 8) * CSTRIDE + col] = make_float2(c[nt][2], c[nt][3]);
        }
        __syncthreads();

        {
            int nb = t << 6;
            int c0 = lane * 4;
            float4 bb  = *(const float4*)&sP[c0];
            float4 gg  = *(const float4*)&sP[DN + c0];
            float4 beb = *(const float4*)&sP[2 * DN + c0];
#pragma unroll
            for (int j = 0; j < 4; ++j) {
                int r = wid * 4 + j;
                int n = nb + r;
                float4 cv = *(const float4*)&sC[r * CSTRIDE + c0];
                float v0 = cv.x + bb.x, v1 = cv.y + bb.y, v2 = cv.z + bb.z, v3 = cv.w + bb.w;
                float s = v0 + v1 + v2 + v3;
                float q = fmaf(v0, v0, fmaf(v1, v1, fmaf(v2, v2, v3 * v3)));
#pragma unroll
                for (int o = 16; o > 0; o >>= 1) {
                    s += __shfl_xor_sync(0xffffffffu, s, o);
                    q += __shfl_xor_sync(0xffffffffu, q, o);
                }
                const float inv = 0.0078125f;
                float mean = s * inv;
                float var  = fmaf(q, inv, -mean * mean);
                float rstd = rsqrtf(var + 1e-5f);
                float o0 = lrelu(fmaf((v0 - mean) * rstd, gg.x, beb.x));
                float o1 = lrelu(fmaf((v1 - mean) * rstd, gg.y, beb.y));
                float o2 = lrelu(fmaf((v2 - mean) * rstd, gg.z, beb.z));
                float o3 = lrelu(fmaf((v3 - mean) * rstd, gg.w, beb.w));
                if (n < N) {
                    float4 xr = *(const float4*)&x[(size_t)n * DN + c0];
                    o0 = lrelu(o0 + xr.x);
                    o1 = lrelu(o1 + xr.y);
                    o2 = lrelu(o2 + xr.z);
                    o3 = lrelu(o3 + xr.w);
                    *(float4*)&out[(size_t)n * DN + c0] = make_float4(o0, o1, o2, o3);
                }
            }
        }
        __syncthreads();
        cur ^= 1;
    }
}

// ---------------- launch ----------------------------------------------------------
extern "C" void kernel_launch(void* const* d_in, const int* in_sizes, int n_in,
                              void* d_out, int out_size)
{
    const float* x   = (const float*)d_in[0];
    const void*  ei  = d_in[1];
    const float* ea  = (const float*)d_in[2];
    const float* W1  = (const float*)d_in[3];
    const float* b1  = (const float*)d_in[4];
    const float* g1  = (const float*)d_in[5];
    const float* be1 = (const float*)d_in[6];
    const float* W2  = (const float*)d_in[7];
    const float* b2  = (const float*)d_in[8];
    const float* g2  = (const float*)d_in[9];
    const float* be2 = (const float*)d_in[10];
    float* out = (float*)d_out;

    int N = in_sizes[0] / DN;
    int E = in_sizes[2] / DE;

    cudaFuncSetAttribute(edge_kernel, cudaFuncAttributeMaxDynamicSharedMemorySize, SMEM_EDGE);
    cudaFuncSetAttribute(node_kernel, cudaFuncAttributeMaxDynamicSharedMemorySize, SMEM_NODE);

    detect_kernel<<<1, 256>>>((const unsigned*)ei, E);
    zero_kernel<<<512, 256>>>(N);
    edge_kernel<<<148, 512, SMEM_EDGE>>>(x, ei, ea, W1, b1, g1, be1, N, E);
    node_kernel<<<148, 512, SMEM_NODE>>>(x, W2, b2, g2, be2, out, N);
}